// round 1
// baseline (speedup 1.0000x reference)
#include <cuda_runtime.h>
#include <cuda_bf16.h>

// ---------------------------------------------------------------------------
// CSAA module: resize conv -> width axial attention -> height axial attention
// -> restore conv.  B=8, R=H=W=128, CIN=COUT=256, fp32.
//
// Round 1: scalar-pipe implementation using packed fma.rn.f32x2 (2 MACs/inst).
// ---------------------------------------------------------------------------

#define BB   8
#define RR   128
#define CIN  256
#define COUT 256
#define HW   16384          // 128*128
#define PAD  132            // smem row pitch in floats (528B, 16B-aligned)

// ---------------- scratch (static device allocations) ----------------------
__device__ float g_resized[BB * RR * HW];   // [b][r][h][w]
__device__ float g_q[BB * RR * HW];         // [b][o][r][s]
__device__ float g_k[BB * RR * HW];
__device__ float g_v[BB * RR * HW];
__device__ float g_wattn[BB * RR * HW];     // [b][r][o][w]  (width-branch out)
__device__ float g_att2[BB * RR * HW];      // [b][o][r][h]  (height-branch out)
__device__ float g_hattn[BB * RR * HW];     // [b][r][h][o]

// ---------------- f32x2 helpers --------------------------------------------
__device__ __forceinline__ void fma2(unsigned long long& d,
                                     unsigned long long a,
                                     unsigned long long b) {
    asm("fma.rn.f32x2 %0, %1, %2, %0;" : "+l"(d) : "l"(a), "l"(b));
}
__device__ __forceinline__ unsigned long long pk(float x, float y) {
    unsigned long long r;
    asm("mov.b64 %0, {%1, %2};" : "=l"(r) : "f"(x), "f"(y));
    return r;
}
__device__ __forceinline__ float2 upk(unsigned long long v) {
    float2 f;
    asm("mov.b64 {%0, %1}, %2;" : "=f"(f.x), "=f"(f.y) : "l"(v));
    return f;
}

// ---------------- shared GEMM inner body ------------------------------------
// As: [KK][PAD] = A transposed (As[k][m]), Bs: [KK][PAD] (Bs[k][n]).
// Thread (ty,tx) computes C rows {ty4..+3, 64+ty4..+3} x cols {tx4..+3, 64+tx4..+3}.
// acc[im][jm][i][jh] holds a float2 pair (cols jm*64+tx4+2*jh, +1).
template <int KK>
__device__ __forceinline__ void gemm_body(const float* __restrict__ As,
                                          const float* __restrict__ Bs,
                                          unsigned long long acc[2][2][4][2],
                                          int ty4, int tx4) {
#pragma unroll 8
    for (int kk = 0; kk < KK; ++kk) {
        const float* ar = As + kk * PAD;
        const float* br = Bs + kk * PAD;
        float4 a0 = *(const float4*)(ar + ty4);
        float4 a1 = *(const float4*)(ar + 64 + ty4);
        unsigned long long b00 = *(const unsigned long long*)(br + tx4);
        unsigned long long b01 = *(const unsigned long long*)(br + tx4 + 2);
        unsigned long long b10 = *(const unsigned long long*)(br + 64 + tx4);
        unsigned long long b11 = *(const unsigned long long*)(br + 64 + tx4 + 2);
        float av[2][4] = {{a0.x, a0.y, a0.z, a0.w}, {a1.x, a1.y, a1.z, a1.w}};
        unsigned long long bv[2][2] = {{b00, b01}, {b10, b11}};
#pragma unroll
        for (int im = 0; im < 2; ++im)
#pragma unroll
            for (int i = 0; i < 4; ++i) {
                unsigned long long ap = pk(av[im][i], av[im][i]);
#pragma unroll
                for (int jm = 0; jm < 2; ++jm) {
                    fma2(acc[im][jm][i][0], ap, bv[jm][0]);
                    fma2(acc[im][jm][i][1], ap, bv[jm][1]);
                }
            }
    }
}

// ---------------- K1: 1x1 conv (resize / restore) ---------------------------
// out[b][m][s] = sum_c W[m][c] * in[b][c][s] + bias[m]
// grid: (HW/128, M/128, B), block (16,16)
__global__ void conv1x1_kernel(const float* __restrict__ in,
                               const float* __restrict__ W,
                               const float* __restrict__ bias,
                               float* __restrict__ out, int M, int K) {
    __shared__ float At[16 * PAD];  // At[k][m]
    __shared__ float Bs[16 * PAD];  // Bs[k][n]
    const int tx = threadIdx.x, ty = threadIdx.y;
    const int tid = ty * 16 + tx;
    const int b = blockIdx.z;
    const int n0 = blockIdx.x * 128;
    const int m0 = blockIdx.y * 128;
    const float* inb = in + (size_t)b * K * HW;

    unsigned long long acc[2][2][4][2] = {};
    for (int k0 = 0; k0 < K; k0 += 16) {
        // A tile: At[kk][mm] = W[(m0+mm)*K + k0+kk]
        for (int i = tid; i < 16 * 128; i += 256) {
            int kk = i & 15, mm = i >> 4;
            At[kk * PAD + mm] = W[(size_t)(m0 + mm) * K + k0 + kk];
        }
        // B tile: Bs[kk][nn] = in[b][k0+kk][n0+nn]
        for (int i = tid; i < 16 * 128; i += 256) {
            int nn = i & 127, kk = i >> 7;
            Bs[kk * PAD + nn] = inb[(size_t)(k0 + kk) * HW + n0 + nn];
        }
        __syncthreads();
        gemm_body<16>(At, Bs, acc, ty * 4, tx * 4);
        __syncthreads();
    }
    float* ob = out + (size_t)b * M * HW;
    const int tx4 = tx * 4, ty4 = ty * 4;
#pragma unroll
    for (int im = 0; im < 2; ++im)
#pragma unroll
        for (int i = 0; i < 4; ++i) {
            int m = m0 + im * 64 + ty4 + i;
            float bv = bias[m];
#pragma unroll
            for (int jm = 0; jm < 2; ++jm) {
                float2 p0 = upk(acc[im][jm][i][0]);
                float2 p1 = upk(acc[im][jm][i][1]);
                float4 val = make_float4(p0.x + bv, p0.y + bv, p1.x + bv, p1.y + bv);
                *(float4*)&ob[(size_t)m * HW + n0 + jm * 64 + tx4] = val;
            }
        }
}

// ---------------- K2: per-(b,r) fused QKV -----------------------------------
// width  (transposeX=0): out[o][n=w] = sum_h Wm[o][h] * X[h][w]
// height (transposeX=1): out[o][n=h] = sum_w Wm[o][w] * X[h][w]
// outputs go to g_{q,k,v}[b][o][r][n].  grid: 1024 = b*128+r, block (16,16).
__global__ void qkv_kernel(const float* __restrict__ in,
                           const float* __restrict__ Wq, const float* __restrict__ bq,
                           const float* __restrict__ Wk, const float* __restrict__ bk,
                           const float* __restrict__ Wv, const float* __restrict__ bv,
                           float* __restrict__ oq, float* __restrict__ ok,
                           float* __restrict__ ov, int transposeX) {
    extern __shared__ float sm[];
    float* Xs = sm;             // [128][PAD]  (Xs[k][n])
    float* Wt = sm + 128 * PAD; // [128][PAD]  (Wt[k][o])
    const int tx = threadIdx.x, ty = threadIdx.y;
    const int tid = ty * 16 + tx;
    const int slice = blockIdx.x;           // b*128 + r
    const int b = slice >> 7, r = slice & 127;
    const float* X = in + (size_t)slice * HW;

    if (!transposeX) {
        for (int i = tid; i < HW; i += 256)
            Xs[(i >> 7) * PAD + (i & 127)] = X[i];
    } else {
        for (int i = tid; i < HW; i += 256) {
            int row = i >> 7, col = i & 127;
            Xs[col * PAD + row] = X[i];
        }
    }

    const float* Ws[3] = {Wq, Wk, Wv};
    const float* bs[3] = {bq, bk, bv};
    float* os[3] = {oq, ok, ov};
    const int tx4 = tx * 4, ty4 = ty * 4;

    for (int m = 0; m < 3; ++m) {
        __syncthreads();  // prior gemm done (and X loaded on first iter)
        for (int i = tid; i < HW; i += 256) {
            int o = i >> 7, kk = i & 127;
            Wt[kk * PAD + o] = Ws[m][i];
        }
        __syncthreads();
        unsigned long long acc[2][2][4][2] = {};
        gemm_body<128>(Wt, Xs, acc, ty4, tx4);

        float* op = os[m] + (size_t)b * 128 * HW + (size_t)r * 128;
#pragma unroll
        for (int im = 0; im < 2; ++im)
#pragma unroll
            for (int i = 0; i < 4; ++i) {
                int o = im * 64 + ty4 + i;
                float bvv = bs[m][o];
#pragma unroll
                for (int jm = 0; jm < 2; ++jm) {
                    float2 p0 = upk(acc[im][jm][i][0]);
                    float2 p1 = upk(acc[im][jm][i][1]);
                    float4 val = make_float4(p0.x + bvv, p0.y + bvv, p1.x + bvv, p1.y + bvv);
                    *(float4*)&op[(size_t)o * HW + jm * 64 + tx4] = val;
                }
            }
    }
}

// ---------------- K3: per-(b,o) attention ------------------------------------
// S[r][u] = sum_s Q[r][s] K[u][s]; P = softmax_rows(S); O[r][s] = sum_u P[r][u] V[u][s]
// mode 0: write O to w_attn[b][r][o][w];  mode 1: write O to g_att2[b][o][r][h].
// grid: 1024 = b*128+o, block (16,16), dyn smem 3*128*PAD floats.
__global__ void attn_kernel(const float* __restrict__ q,
                            const float* __restrict__ k,
                            const float* __restrict__ v,
                            float* __restrict__ out, int mode) {
    extern __shared__ float sm[];
    float* Qt = sm;              // Qt[s][r]; later reused as Vs[u][s]
    float* Kt = sm + 128 * PAD;  // Kt[s][u]; later reused as Pt[u][r]
    float* Ss = sm + 2 * 128 * PAD;  // Ss[r][u]
    const int tx = threadIdx.x, ty = threadIdx.y;
    const int tid = ty * 16 + tx;
    const int slice = blockIdx.x;  // b*128 + o
    const int b = slice >> 7, o = slice & 127;
    const float* Q = q + (size_t)slice * HW;
    const float* Kp = k + (size_t)slice * HW;
    const float* Vp = v + (size_t)slice * HW;
    const int tx4 = tx * 4, ty4 = ty * 4;

    // load Q, K transposed: Qt[s][r] = Q[r][s]
    for (int i = tid; i < HW; i += 256) {
        int row = i >> 7, s = i & 127;
        Qt[s * PAD + row] = Q[i];
        Kt[s * PAD + row] = Kp[i];
    }
    __syncthreads();

    {
        unsigned long long acc[2][2][4][2] = {};
        gemm_body<128>(Qt, Kt, acc, ty4, tx4);
#pragma unroll
        for (int im = 0; im < 2; ++im)
#pragma unroll
            for (int i = 0; i < 4; ++i) {
                int rrow = im * 64 + ty4 + i;
#pragma unroll
                for (int jm = 0; jm < 2; ++jm) {
                    float2 p0 = upk(acc[im][jm][i][0]);
                    float2 p1 = upk(acc[im][jm][i][1]);
                    float4 val = make_float4(p0.x, p0.y, p1.x, p1.y);
                    *(float4*)&Ss[rrow * PAD + jm * 64 + tx4] = val;
                }
            }
    }
    __syncthreads();

    // V -> Qt buffer (row major [u][s]); softmax of Ss rows -> Pt (=Kt) transposed
    for (int i = tid; i < HW; i += 256)
        Qt[(i >> 7) * PAD + (i & 127)] = Vp[i];

    if (tid < 128) {
        float* row = Ss + tid * PAD;
        float mx = -3.4e38f;
#pragma unroll 4
        for (int u = 0; u < 128; ++u) mx = fmaxf(mx, row[u]);
        float s = 0.f;
#pragma unroll 4
        for (int u = 0; u < 128; ++u) {
            float e = expf(row[u] - mx);
            row[u] = e;
            s += e;
        }
        float inv = 1.f / s;
#pragma unroll 4
        for (int u = 0; u < 128; ++u) Kt[u * PAD + tid] = row[u] * inv;
    }
    __syncthreads();

    unsigned long long acc[2][2][4][2] = {};
    gemm_body<128>(Kt, Qt, acc, ty4, tx4);  // O[r][s] = sum_u Pt[u][r] Vs[u][s]

    if (mode == 0) {
        // w_attn[((b*128+r)*128+o)*128 + s]
        float* base = out + (size_t)b * 128 * HW + (size_t)o * 128;
#pragma unroll
        for (int im = 0; im < 2; ++im)
#pragma unroll
            for (int i = 0; i < 4; ++i) {
                int rrow = im * 64 + ty4 + i;
#pragma unroll
                for (int jm = 0; jm < 2; ++jm) {
                    float2 p0 = upk(acc[im][jm][i][0]);
                    float2 p1 = upk(acc[im][jm][i][1]);
                    float4 val = make_float4(p0.x, p0.y, p1.x, p1.y);
                    *(float4*)&base[(size_t)rrow * HW + jm * 64 + tx4] = val;
                }
            }
    } else {
        // g_att2[b][o][r][s] contiguous
        float* base = out + (size_t)slice * HW;
#pragma unroll
        for (int im = 0; im < 2; ++im)
#pragma unroll
            for (int i = 0; i < 4; ++i) {
                int rrow = im * 64 + ty4 + i;
#pragma unroll
                for (int jm = 0; jm < 2; ++jm) {
                    float2 p0 = upk(acc[im][jm][i][0]);
                    float2 p1 = upk(acc[im][jm][i][1]);
                    float4 val = make_float4(p0.x, p0.y, p1.x, p1.y);
                    *(float4*)&base[rrow * 128 + jm * 64 + tx4] = val;
                }
            }
    }
}

// ---------------- K4: transpose g_att2[b][o][r][h] -> g_hattn[b][r][h][o] ---
// grid (4,4,1024), block (32,8)
__global__ void trans_kernel(const float* __restrict__ in, float* __restrict__ out) {
    __shared__ float t[32][33];
    const int slice = blockIdx.z;  // b*128 + r
    const int b = slice >> 7, r = slice & 127;
    const int o0 = blockIdx.x * 32, h0 = blockIdx.y * 32;
#pragma unroll
    for (int i = threadIdx.y; i < 32; i += 8)
        t[i][threadIdx.x] =
            in[(((size_t)b * 128 + o0 + i) * 128 + r) * 128 + h0 + threadIdx.x];
    __syncthreads();
#pragma unroll
    for (int i = threadIdx.y; i < 32; i += 8)
        out[(((size_t)b * 128 + r) * 128 + h0 + i) * 128 + o0 + threadIdx.x] =
            t[threadIdx.x][i];
}

// ---------------------------------------------------------------------------
extern "C" void kernel_launch(void* const* d_in, const int* in_sizes, int n_in,
                              void* d_out, int out_size) {
    const float* x   = (const float*)d_in[0];
    const float* Wr  = (const float*)d_in[1];
    const float* br  = (const float*)d_in[2];
    const float* Wqw = (const float*)d_in[3];
    const float* bqw = (const float*)d_in[4];
    const float* Wkw = (const float*)d_in[5];
    const float* bkw = (const float*)d_in[6];
    const float* Wvw = (const float*)d_in[7];
    const float* bvw = (const float*)d_in[8];
    const float* Wqh = (const float*)d_in[9];
    const float* bqh = (const float*)d_in[10];
    const float* Wkh = (const float*)d_in[11];
    const float* bkh = (const float*)d_in[12];
    const float* Wvh = (const float*)d_in[13];
    const float* bvh = (const float*)d_in[14];
    const float* Wo  = (const float*)d_in[15];
    const float* bo  = (const float*)d_in[16];
    float* out = (float*)d_out;

    void *p_res, *p_q, *p_k, *p_v, *p_wa, *p_a2, *p_ha;
    cudaGetSymbolAddress(&p_res, g_resized);
    cudaGetSymbolAddress(&p_q, g_q);
    cudaGetSymbolAddress(&p_k, g_k);
    cudaGetSymbolAddress(&p_v, g_v);
    cudaGetSymbolAddress(&p_wa, g_wattn);
    cudaGetSymbolAddress(&p_a2, g_att2);
    cudaGetSymbolAddress(&p_ha, g_hattn);
    float* res = (float*)p_res;
    float* qb = (float*)p_q;
    float* kb = (float*)p_k;
    float* vb = (float*)p_v;
    float* wa = (float*)p_wa;
    float* a2 = (float*)p_a2;
    float* ha = (float*)p_ha;

    const int SMEM_QKV = 2 * 128 * PAD * 4;  // 135168
    const int SMEM_ATT = 3 * 128 * PAD * 4;  // 202752
    cudaFuncSetAttribute((const void*)qkv_kernel,
                         cudaFuncAttributeMaxDynamicSharedMemorySize, SMEM_QKV);
    cudaFuncSetAttribute((const void*)attn_kernel,
                         cudaFuncAttributeMaxDynamicSharedMemorySize, SMEM_ATT);

    dim3 blk(16, 16);
    // 1) resize conv: x[8,256,HW] -> resized[8,128,HW]
    conv1x1_kernel<<<dim3(128, 1, 8), blk>>>(x, Wr, br, res, 128, 256);
    // 2) width qkv
    qkv_kernel<<<1024, blk, SMEM_QKV>>>(res, Wqw, bqw, Wkw, bkw, Wvw, bvw,
                                        qb, kb, vb, 0);
    // 3) width attention -> w_attn[b][r][o][w]
    attn_kernel<<<1024, blk, SMEM_ATT>>>(qb, kb, vb, wa, 0);
    // 4) height qkv (transposed slice read)
    qkv_kernel<<<1024, blk, SMEM_QKV>>>(wa, Wqh, bqh, Wkh, bkh, Wvh, bvh,
                                        qb, kb, vb, 1);
    // 5) height attention -> g_att2[b][o][r][h]
    attn_kernel<<<1024, blk, SMEM_ATT>>>(qb, kb, vb, a2, 1);
    // 6) transpose -> h_attn[b][r][h][o]
    trans_kernel<<<dim3(4, 4, 1024), dim3(32, 8)>>>(a2, ha);
    // 7) restore conv: h_attn[8,128,HW] -> out[8,256,HW]
    conv1x1_kernel<<<dim3(128, 2, 8), blk>>>(ha, Wo, bo, out, 256, 128);
}

// round 4
// speedup vs baseline: 1.5236x; 1.5236x over previous
#include <cuda_runtime.h>
#include <cuda_bf16.h>
#include <stdint.h>

// ---------------------------------------------------------------------------
// CSAA via warp-level bf16 mma.sync (m16n8k16) with hi/lo split precision
// (3-term: Ahi*Bhi + Alo*Bhi + Ahi*Blo), fp32 accumulate.
// Works on baseline compute_100 PTX (no sm_100a-only instructions).
// ---------------------------------------------------------------------------

#define BB   8
#define HW   16384

__device__ float g_resized[BB * 128 * HW];
__device__ float g_q[BB * 128 * HW];
__device__ float g_k[BB * 128 * HW];
__device__ float g_v[BB * 128 * HW];
__device__ float g_wattn[BB * 128 * HW];   // [b][r][h][w]
__device__ float g_att2[BB * 128 * HW];    // [b][o][r][h]
__device__ float g_hattn[BB * 128 * HW];   // [b][r][h][o]

// ---------------- smem layout (bytes) ---------------------------------------
// bf16 tiles 128 rows x 128 cols, pitch 272B (136 halves, conflict-free ldmatrix)
#define TP        272
#define TILE_B    34816              // 128*272
#define T_AH      0
#define T_AL      34816
#define T_BH      69632
#define T_BL      104448
#define T_STAGE   139264             // fp32 stage 128 x 132
#define SP        132                // stage pitch (floats)
#define SMEM_TOT  206848

// ---------------- PTX helpers ----------------------------------------------
__device__ __forceinline__ uint32_t smem_u32(const void* p) {
    uint32_t a;
    asm("{ .reg .u64 t; cvta.to.shared.u64 t, %1; cvt.u32.u64 %0, t; }" : "=r"(a) : "l"(p));
    return a;
}
__device__ __forceinline__ void ldsm4(uint32_t (&r)[4], uint32_t a) {
    asm volatile("ldmatrix.sync.aligned.m8n8.x4.shared.b16 {%0,%1,%2,%3}, [%4];"
                 : "=r"(r[0]), "=r"(r[1]), "=r"(r[2]), "=r"(r[3]) : "r"(a));
}
__device__ __forceinline__ void ldsm4t(uint32_t (&r)[4], uint32_t a) {
    asm volatile("ldmatrix.sync.aligned.m8n8.x4.trans.shared.b16 {%0,%1,%2,%3}, [%4];"
                 : "=r"(r[0]), "=r"(r[1]), "=r"(r[2]), "=r"(r[3]) : "r"(a));
}
__device__ __forceinline__ void mma_bf16(float (&c)[4], const uint32_t (&a)[4],
                                         const uint32_t (&b)[2]) {
    asm volatile(
        "mma.sync.aligned.m16n8k16.row.col.f32.bf16.bf16.f32 "
        "{%0,%1,%2,%3}, {%4,%5,%6,%7}, {%8,%9}, {%0,%1,%2,%3};"
        : "+f"(c[0]), "+f"(c[1]), "+f"(c[2]), "+f"(c[3])
        : "r"(a[0]), "r"(a[1]), "r"(a[2]), "r"(a[3]), "r"(b[0]), "r"(b[1]));
}
__device__ __forceinline__ uint32_t pkbf(__nv_bfloat16 a, __nv_bfloat16 b) {
    __nv_bfloat162 t(a, b);
    return *reinterpret_cast<uint32_t*>(&t);
}

// ---------------- tile loader: fp32 [128][gs] -> hi/lo bf16 tiles -----------
// Writes rows row=0..127 (source row stride gs floats), cols 0..127.
__device__ __forceinline__ void load_hilo(char* sm, int off, const float* __restrict__ g,
                                          long gs, int tid) {
    for (int i = tid * 4; i < 16384; i += 1024) {
        int row = i >> 7, col = i & 127;
        float4 x = *(const float4*)(g + (long)row * gs + col);
        __nv_bfloat16 h0 = __float2bfloat16(x.x), h1 = __float2bfloat16(x.y);
        __nv_bfloat16 h2 = __float2bfloat16(x.z), h3 = __float2bfloat16(x.w);
        __nv_bfloat16 l0 = __float2bfloat16(x.x - __bfloat162float(h0));
        __nv_bfloat16 l1 = __float2bfloat16(x.y - __bfloat162float(h1));
        __nv_bfloat16 l2 = __float2bfloat16(x.z - __bfloat162float(h2));
        __nv_bfloat16 l3 = __float2bfloat16(x.w - __bfloat162float(h3));
        char* p = sm + off + row * TP + col * 2;
        *(uint2*)p = make_uint2(pkbf(h0, h1), pkbf(h2, h3));
        *(uint2*)(p + TILE_B) = make_uint2(pkbf(l0, l1), pkbf(l2, l3));
    }
}

// ---------------- warp GEMM 128x128x128, 3-term split ------------------------
// BT=true : B tile holds row-major KxN  (ldmatrix.trans)
// BT=false: B tile holds row-major NxK  (ldmatrix, B-frag via X=B^T)
template <bool BT>
__device__ __forceinline__ void warp_gemm(uint32_t sa, uint32_t sb,
                                          float (&C)[2][8][4], int lane,
                                          int wm, int wn) {
    const int lh = lane & 15, lq = lane >> 4;  // lq in {0,1}
#pragma unroll 2
    for (int k0 = 0; k0 < 128; k0 += 16) {
        uint32_t ah[2][4], al[2][4];
#pragma unroll
        for (int mt = 0; mt < 2; ++mt) {
            uint32_t addr = sa + (wm * 32 + mt * 16 + lh) * TP + (k0 + lq * 8) * 2;
            ldsm4(ah[mt], addr);
            ldsm4(al[mt], addr + TILE_B);
        }
        uint32_t bh[8][2], bl[8][2];
#pragma unroll
        for (int ng = 0; ng < 4; ++ng) {
            uint32_t r[4], rl[4], addr;
            if (BT) {
                addr = sb + (k0 + lh) * TP + (wn * 64 + ng * 16 + lq * 8) * 2;
                ldsm4t(r, addr);
                ldsm4t(rl, addr + TILE_B);
            } else {
                addr = sb + (wn * 64 + ng * 16 + lq * 8 + (lane & 7)) * TP +
                       (k0 + ((lane >> 3) & 1) * 8) * 2;
                ldsm4(r, addr);
                ldsm4(rl, addr + TILE_B);
            }
            bh[2 * ng][0] = r[0];  bh[2 * ng][1] = r[1];
            bh[2 * ng + 1][0] = r[2]; bh[2 * ng + 1][1] = r[3];
            bl[2 * ng][0] = rl[0]; bl[2 * ng][1] = rl[1];
            bl[2 * ng + 1][0] = rl[2]; bl[2 * ng + 1][1] = rl[3];
        }
#pragma unroll
        for (int mt = 0; mt < 2; ++mt)
#pragma unroll
            for (int nb = 0; nb < 8; ++nb) {
                mma_bf16(C[mt][nb], ah[mt], bh[nb]);
                mma_bf16(C[mt][nb], al[mt], bh[nb]);
                mma_bf16(C[mt][nb], ah[mt], bl[nb]);
            }
    }
}

__device__ __forceinline__ void frags_to_stage(float* stage, float (&C)[2][8][4],
                                               int lane, int wm, int wn) {
    const int r0 = wm * 32 + (lane >> 2);
    const int c0 = wn * 64 + 2 * (lane & 3);
#pragma unroll
    for (int mt = 0; mt < 2; ++mt)
#pragma unroll
        for (int nb = 0; nb < 8; ++nb) {
            int row = r0 + mt * 16, col = c0 + nb * 8;
            *(float2*)&stage[row * SP + col] = make_float2(C[mt][nb][0], C[mt][nb][1]);
            *(float2*)&stage[(row + 8) * SP + col] = make_float2(C[mt][nb][2], C[mt][nb][3]);
        }
}

// stage -> global (row stride rs floats), optional per-row bias
__device__ __forceinline__ void stage_to_global(const float* stage, float* out, long rs,
                                                const float* bias, int tid) {
    for (int fi = tid; fi < 128 * 32; fi += 256) {
        int row = fi >> 5, c4 = (fi & 31) * 4;
        float4 v = *(const float4*)&stage[row * SP + c4];
        if (bias) {
            float bv = bias[row];
            v.x += bv; v.y += bv; v.z += bv; v.w += bv;
        }
        *(float4*)(out + (long)row * rs + c4) = v;
    }
}

// ---------------- K1: 1x1 conv ----------------------------------------------
// grid (HW/128, M/128, B); out[b][m][s] = sum_c W[m][c] in[b][c][s] + bias[m]
__global__ void __launch_bounds__(256, 1)
conv_mma(const float* __restrict__ in, const float* __restrict__ W,
         const float* __restrict__ bias, float* __restrict__ out, int K, int Mtot) {
    extern __shared__ char sm[];
    const int tid = threadIdx.x, lane = tid & 31, w = tid >> 5;
    const int wm = w >> 1, wn = w & 1;
    const uint32_t su = smem_u32(sm);
    const int n0 = blockIdx.x * 128, m0 = blockIdx.y * 128, b = blockIdx.z;
    const float* inb = in + (size_t)b * K * HW;

    float C[2][8][4] = {};
    for (int kh = 0; kh < (K >> 7); ++kh) {
        load_hilo(sm, T_AH, W + (size_t)m0 * K + kh * 128, K, tid);        // A[m][c]
        load_hilo(sm, T_BH, inb + (size_t)kh * 128 * HW + n0, HW, tid);    // B[c][n]
        __syncthreads();
        warp_gemm<true>(su + T_AH, su + T_BH, C, lane, wm, wn);
        __syncthreads();
    }
    float* stage = (float*)(sm + T_STAGE);
    frags_to_stage(stage, C, lane, wm, wn);
    __syncthreads();
    stage_to_global(stage, out + (size_t)b * Mtot * HW + (size_t)m0 * HW + n0, HW,
                    bias + m0, tid);
}

// ---------------- K2: per-(b,r) QKV -----------------------------------------
// grid 1024 = b*128+r.
// bt=1 (width):  out[o][w] = sum_h W[o][h] X[h][w]  (X row-major KxN)
// bt=0 (height): out[o][h] = sum_w W[o][w] X[h][w]  (X row-major NxK)
__global__ void __launch_bounds__(256, 1)
qkv_mma(const float* __restrict__ in,
        const float* __restrict__ Wq, const float* __restrict__ bq,
        const float* __restrict__ Wk, const float* __restrict__ bk,
        const float* __restrict__ Wv, const float* __restrict__ bv,
        float* __restrict__ oq, float* __restrict__ okk, float* __restrict__ ov,
        int bt) {
    extern __shared__ char sm[];
    const int tid = threadIdx.x, lane = tid & 31, w = tid >> 5;
    const int wm = w >> 1, wn = w & 1;
    const uint32_t su = smem_u32(sm);
    const int slice = blockIdx.x;
    const int b = slice >> 7, r = slice & 127;

    load_hilo(sm, T_BH, in + (size_t)slice * HW, 128, tid);  // X

    const float* Ws[3] = {Wq, Wk, Wv};
    const float* bs[3] = {bq, bk, bv};
    float* os[3] = {oq, okk, ov};
    float* stage = (float*)(sm + T_STAGE);

    for (int m = 0; m < 3; ++m) {
        load_hilo(sm, T_AH, Ws[m], 128, tid);
        __syncthreads();
        float C[2][8][4] = {};
        if (bt) warp_gemm<true>(su + T_AH, su + T_BH, C, lane, wm, wn);
        else    warp_gemm<false>(su + T_AH, su + T_BH, C, lane, wm, wn);
        frags_to_stage(stage, C, lane, wm, wn);
        __syncthreads();
        stage_to_global(stage, os[m] + (size_t)b * 128 * HW + (size_t)r * 128, HW,
                        bs[m], tid);
        __syncthreads();
    }
}

// ---------------- K3: per-(b,o) attention ------------------------------------
// S = Q K^T; P = softmax rows; O = P V
// mode0 -> w_attn[b][r][o][w]; mode1 -> g_att2[b][o][r][h]
__global__ void __launch_bounds__(256, 1)
attn_mma(const float* __restrict__ q, const float* __restrict__ k,
         const float* __restrict__ v, float* __restrict__ out, int mode) {
    extern __shared__ char sm[];
    const int tid = threadIdx.x, lane = tid & 31, w = tid >> 5;
    const int wm = w >> 1, wn = w & 1;
    const uint32_t su = smem_u32(sm);
    const int slice = blockIdx.x;
    const int b = slice >> 7, o = slice & 127;
    float* stage = (float*)(sm + T_STAGE);

    load_hilo(sm, T_AH, q + (size_t)slice * HW, 128, tid);  // Q[r][s]
    load_hilo(sm, T_BH, k + (size_t)slice * HW, 128, tid);  // K[u][s] (NxK)
    __syncthreads();
    {
        float C[2][8][4] = {};
        warp_gemm<false>(su + T_AH, su + T_BH, C, lane, wm, wn);
        frags_to_stage(stage, C, lane, wm, wn);
    }
    __syncthreads();

    // V -> B tiles ([u][s] row-major KxN); softmax rows of S -> P hi/lo into A
    load_hilo(sm, T_BH, v + (size_t)slice * HW, 128, tid);
    if (tid < 128) {
        float s[128];
#pragma unroll
        for (int u4 = 0; u4 < 32; ++u4) {
            float4 x = *(const float4*)&stage[tid * SP + u4 * 4];
            s[4 * u4] = x.x; s[4 * u4 + 1] = x.y; s[4 * u4 + 2] = x.z; s[4 * u4 + 3] = x.w;
        }
        float mx = s[0];
#pragma unroll
        for (int u = 1; u < 128; ++u) mx = fmaxf(mx, s[u]);
        float sum = 0.f;
#pragma unroll
        for (int u = 0; u < 128; ++u) {
            float e = __expf(s[u] - mx);
            s[u] = e;
            sum += e;
        }
        float inv = 1.f / sum;
        char* ph = sm + T_AH + tid * TP;
#pragma unroll
        for (int u = 0; u < 128; u += 2) {
            float x0 = s[u] * inv, x1 = s[u + 1] * inv;
            __nv_bfloat16 h0 = __float2bfloat16(x0), h1 = __float2bfloat16(x1);
            __nv_bfloat16 l0 = __float2bfloat16(x0 - __bfloat162float(h0));
            __nv_bfloat16 l1 = __float2bfloat16(x1 - __bfloat162float(h1));
            *(uint32_t*)(ph + u * 2) = pkbf(h0, h1);
            *(uint32_t*)(ph + TILE_B + u * 2) = pkbf(l0, l1);
        }
    }
    __syncthreads();

    float C[2][8][4] = {};
    warp_gemm<true>(su + T_AH, su + T_BH, C, lane, wm, wn);  // O = P V
    __syncthreads();
    frags_to_stage(stage, C, lane, wm, wn);
    __syncthreads();

    float* ob;
    long rs;
    if (mode == 0) { ob = out + (size_t)b * 128 * HW + (size_t)o * 128; rs = HW; }
    else           { ob = out + (size_t)slice * HW;                     rs = 128; }
    stage_to_global(stage, ob, rs, nullptr, tid);
}

// ---------------- K4: transpose [b][o][r][h] -> [b][r][h][o] -----------------
__global__ void trans_kernel(const float* __restrict__ in, float* __restrict__ out) {
    __shared__ float t[32][33];
    const int slice = blockIdx.z;
    const int b = slice >> 7, r = slice & 127;
    const int o0 = blockIdx.x * 32, h0 = blockIdx.y * 32;
#pragma unroll
    for (int i = threadIdx.y; i < 32; i += 8)
        t[i][threadIdx.x] =
            in[(((size_t)b * 128 + o0 + i) * 128 + r) * 128 + h0 + threadIdx.x];
    __syncthreads();
#pragma unroll
    for (int i = threadIdx.y; i < 32; i += 8)
        out[(((size_t)b * 128 + r) * 128 + h0 + i) * 128 + o0 + threadIdx.x] =
            t[threadIdx.x][i];
}

// ---------------------------------------------------------------------------
extern "C" void kernel_launch(void* const* d_in, const int* in_sizes, int n_in,
                              void* d_out, int out_size) {
    const float* x   = (const float*)d_in[0];
    const float* Wr  = (const float*)d_in[1];
    const float* br  = (const float*)d_in[2];
    const float* Wqw = (const float*)d_in[3];
    const float* bqw = (const float*)d_in[4];
    const float* Wkw = (const float*)d_in[5];
    const float* bkw = (const float*)d_in[6];
    const float* Wvw = (const float*)d_in[7];
    const float* bvw = (const float*)d_in[8];
    const float* Wqh = (const float*)d_in[9];
    const float* bqh = (const float*)d_in[10];
    const float* Wkh = (const float*)d_in[11];
    const float* bkh = (const float*)d_in[12];
    const float* Wvh = (const float*)d_in[13];
    const float* bvh = (const float*)d_in[14];
    const float* Wo  = (const float*)d_in[15];
    const float* bo  = (const float*)d_in[16];
    float* out = (float*)d_out;

    void *p_res, *p_q, *p_k, *p_v, *p_wa, *p_a2, *p_ha;
    cudaGetSymbolAddress(&p_res, g_resized);
    cudaGetSymbolAddress(&p_q, g_q);
    cudaGetSymbolAddress(&p_k, g_k);
    cudaGetSymbolAddress(&p_v, g_v);
    cudaGetSymbolAddress(&p_wa, g_wattn);
    cudaGetSymbolAddress(&p_a2, g_att2);
    cudaGetSymbolAddress(&p_ha, g_hattn);
    float* res = (float*)p_res;
    float* qb = (float*)p_q;
    float* kb = (float*)p_k;
    float* vb = (float*)p_v;
    float* wa = (float*)p_wa;
    float* a2 = (float*)p_a2;
    float* ha = (float*)p_ha;

    cudaFuncSetAttribute((const void*)conv_mma,
                         cudaFuncAttributeMaxDynamicSharedMemorySize, SMEM_TOT);
    cudaFuncSetAttribute((const void*)qkv_mma,
                         cudaFuncAttributeMaxDynamicSharedMemorySize, SMEM_TOT);
    cudaFuncSetAttribute((const void*)attn_mma,
                         cudaFuncAttributeMaxDynamicSharedMemorySize, SMEM_TOT);

    // 1) resize conv: x[8,256,HW] -> resized[8,128,HW]
    conv_mma<<<dim3(128, 1, BB), 256, SMEM_TOT>>>(x, Wr, br, res, 256, 128);
    // 2) width qkv: mixes over H (X[h][w] is KxN -> bt=1)
    qkv_mma<<<1024, 256, SMEM_TOT>>>(res, Wqw, bqw, Wkw, bkw, Wvw, bvw,
                                     qb, kb, vb, 1);
    // 3) width attention -> w_attn[b][r][o][w]
    attn_mma<<<1024, 256, SMEM_TOT>>>(qb, kb, vb, wa, 0);
    // 4) height qkv: mixes over W (X[h][w] is NxK -> bt=0)
    qkv_mma<<<1024, 256, SMEM_TOT>>>(wa, Wqh, bqh, Wkh, bkh, Wvh, bvh,
                                     qb, kb, vb, 0);
    // 5) height attention -> g_att2[b][o][r][h]
    attn_mma<<<1024, 256, SMEM_TOT>>>(qb, kb, vb, a2, 1);
    // 6) transpose -> h_attn[b][r][h][o]
    trans_kernel<<<dim3(4, 4, 1024), dim3(32, 8)>>>(a2, ha);
    // 7) restore conv: h_attn[8,128,HW] -> out[8,256,HW]
    conv_mma<<<dim3(128, 2, BB), 256, SMEM_TOT>>>(ha, Wo, bo, out, 128, 256);
}

// round 7
// speedup vs baseline: 2.9643x; 1.9456x over previous
#include <cuda_runtime.h>
#include <cuda_bf16.h>
#include <stdint.h>

// ---------------------------------------------------------------------------
// CSAA via warp-level bf16 mma.sync m16n8k16, hi/lo split precision (3-term),
// bf16 hi/lo planes in global for all GEMM operands, cp.async pipelined tile
// loads, 512-thread CTAs, fragment-direct epilogues.
// ---------------------------------------------------------------------------

#define SL    16384                       // elements per 128x128 slice
#define TEN   (8 * 128 * SL)              // elements per [8,128,128,128] tensor
#define TP    272                         // smem tile pitch (bytes)
#define TILE_B 34816                      // one bf16 plane tile (128*272)
#define PLANE  69632                      // hi+lo pair

// ---------------- scratch ---------------------------------------------------
__device__ __nv_bfloat16 g_resh[TEN], g_resl[TEN];
__device__ __nv_bfloat16 g_qh[TEN], g_ql[TEN];
__device__ __nv_bfloat16 g_kh[TEN], g_kl[TEN];
__device__ __nv_bfloat16 g_vh[TEN], g_vl[TEN];
__device__ __nv_bfloat16 g_wah[TEN], g_wal[TEN];   // w_attn planes [b][r][o][w]
__device__ float         g_att2[TEN];              // [b][o][r][h] fp32
__device__ __nv_bfloat16 g_hah[TEN], g_hal[TEN];   // h_attn planes [b][r][h*128+o]
__device__ __nv_bfloat16 g_wth[163840], g_wtl[163840];  // weight planes

// weight plane offsets
#define W_R   0
#define W_QW  32768
#define W_KW  49152
#define W_VW  65536
#define W_QH  81920
#define W_KH  98304
#define W_VH  114688
#define W_O   131072

// ---------------- PTX helpers ----------------------------------------------
__device__ __forceinline__ uint32_t smem_u32(const void* p) {
    uint32_t a;
    asm("{ .reg .u64 t; cvta.to.shared.u64 t, %1; cvt.u32.u64 %0, t; }" : "=r"(a) : "l"(p));
    return a;
}
__device__ __forceinline__ void ldsm4(uint32_t (&r)[4], uint32_t a) {
    asm volatile("ldmatrix.sync.aligned.m8n8.x4.shared.b16 {%0,%1,%2,%3}, [%4];"
                 : "=r"(r[0]), "=r"(r[1]), "=r"(r[2]), "=r"(r[3]) : "r"(a));
}
__device__ __forceinline__ void ldsm4t(uint32_t (&r)[4], uint32_t a) {
    asm volatile("ldmatrix.sync.aligned.m8n8.x4.trans.shared.b16 {%0,%1,%2,%3}, [%4];"
                 : "=r"(r[0]), "=r"(r[1]), "=r"(r[2]), "=r"(r[3]) : "r"(a));
}
__device__ __forceinline__ void mma_bf16(float (&c)[4], const uint32_t (&a)[4],
                                         const uint32_t (&b)[2]) {
    asm volatile(
        "mma.sync.aligned.m16n8k16.row.col.f32.bf16.bf16.f32 "
        "{%0,%1,%2,%3}, {%4,%5,%6,%7}, {%8,%9}, {%0,%1,%2,%3};"
        : "+f"(c[0]), "+f"(c[1]), "+f"(c[2]), "+f"(c[3])
        : "r"(a[0]), "r"(a[1]), "r"(a[2]), "r"(a[3]), "r"(b[0]), "r"(b[1]));
}
__device__ __forceinline__ uint32_t pkbf(__nv_bfloat16 a, __nv_bfloat16 b) {
    __nv_bfloat162 t(a, b);
    return *reinterpret_cast<uint32_t*>(&t);
}
__device__ __forceinline__ void cpa16(uint32_t d, const void* s) {
    asm volatile("cp.async.cg.shared.global [%0], [%1], 16;" :: "r"(d), "l"(s) : "memory");
}
__device__ __forceinline__ void cpa_commit() {
    asm volatile("cp.async.commit_group;" ::: "memory");
}
template <int N>
__device__ __forceinline__ void cpa_wait() {
    asm volatile("cp.async.wait_group %0;" :: "n"(N) : "memory");
}

// ---------------- tile loaders ----------------------------------------------
// bf16 plane pair -> smem (hi at sdst, lo at sdst+TILE_B), 128 rows x 256B
__device__ __forceinline__ void cpa_tile(uint32_t sdst, const __nv_bfloat16* gh,
                                         const __nv_bfloat16* gl, long grs, int tid) {
#pragma unroll
    for (int i = tid; i < 2048; i += 512) {
        int row = i >> 4, cc = i & 15;
        uint32_t d = sdst + row * TP + cc * 16;
        cpa16(d, (const char*)(gh + (long)row * grs) + cc * 16);
        cpa16(d + TILE_B, (const char*)(gl + (long)row * grs) + cc * 16);
    }
}
// fp32 global -> hi/lo smem tiles (for x in resize conv)
__device__ __forceinline__ void load_hilo_f32(char* sm, int off, const float* __restrict__ g,
                                              long gs, int tid) {
    for (int i = tid * 4; i < 16384; i += 2048) {
        int row = i >> 7, col = i & 127;
        float4 x = *(const float4*)(g + (long)row * gs + col);
        __nv_bfloat16 h0 = __float2bfloat16(x.x), h1 = __float2bfloat16(x.y);
        __nv_bfloat16 h2 = __float2bfloat16(x.z), h3 = __float2bfloat16(x.w);
        __nv_bfloat16 l0 = __float2bfloat16(x.x - __bfloat162float(h0));
        __nv_bfloat16 l1 = __float2bfloat16(x.y - __bfloat162float(h1));
        __nv_bfloat16 l2 = __float2bfloat16(x.z - __bfloat162float(h2));
        __nv_bfloat16 l3 = __float2bfloat16(x.w - __bfloat162float(h3));
        char* p = sm + off + row * TP + col * 2;
        *(uint2*)p = make_uint2(pkbf(h0, h1), pkbf(h2, h3));
        *(uint2*)(p + TILE_B) = make_uint2(pkbf(l0, l1), pkbf(l2, l3));
    }
}

// ---------------- warp GEMM 128x128x128, 16 warps (4x4), 3-term split -------
// BT=true : B tile holds row-major KxN (ldmatrix.trans)
// BT=false: B tile holds row-major NxK (ldmatrix)
template <bool BT>
__device__ __forceinline__ void wgemm(uint32_t sa, uint32_t sb, float (&C)[2][4][4],
                                      int lane, int wm, int wn) {
    const int lh = lane & 15, lq = lane >> 4;
#pragma unroll
    for (int k0 = 0; k0 < 128; k0 += 16) {
        uint32_t ah[2][4], al[2][4];
#pragma unroll
        for (int mt = 0; mt < 2; ++mt) {
            uint32_t addr = sa + (wm * 32 + mt * 16 + lh) * TP + (k0 + lq * 8) * 2;
            ldsm4(ah[mt], addr);
            ldsm4(al[mt], addr + TILE_B);
        }
        uint32_t bh[4][2], bl[4][2];
#pragma unroll
        for (int ng = 0; ng < 2; ++ng) {
            uint32_t r[4], rl[4], addr;
            if (BT) {
                addr = sb + (k0 + lh) * TP + (wn * 32 + ng * 16 + lq * 8) * 2;
                ldsm4t(r, addr);
                ldsm4t(rl, addr + TILE_B);
            } else {
                addr = sb + (wn * 32 + ng * 16 + lq * 8 + (lane & 7)) * TP +
                       (k0 + ((lane >> 3) & 1) * 8) * 2;
                ldsm4(r, addr);
                ldsm4(rl, addr + TILE_B);
            }
            bh[2 * ng][0] = r[0];     bh[2 * ng][1] = r[1];
            bh[2 * ng + 1][0] = r[2]; bh[2 * ng + 1][1] = r[3];
            bl[2 * ng][0] = rl[0];    bl[2 * ng][1] = rl[1];
            bl[2 * ng + 1][0] = rl[2]; bl[2 * ng + 1][1] = rl[3];
        }
#pragma unroll
        for (int mt = 0; mt < 2; ++mt)
#pragma unroll
            for (int nb = 0; nb < 4; ++nb) {
                mma_bf16(C[mt][nb], ah[mt], bh[nb]);
                mma_bf16(C[mt][nb], al[mt], bh[nb]);
                mma_bf16(C[mt][nb], ah[mt], bl[nb]);
            }
    }
}

// ---------------- fragment-direct epilogues ---------------------------------
__device__ __forceinline__ void store_planes(float (&C)[2][4][4],
        __nv_bfloat16* __restrict__ ph, __nv_bfloat16* __restrict__ pl,
        long rstr, const float* __restrict__ bias, int lane, int wm, int wn) {
    const int c0 = wn * 32 + 2 * (lane & 3);
#pragma unroll
    for (int mt = 0; mt < 2; ++mt) {
        int r0 = wm * 32 + mt * 16 + (lane >> 2);
#pragma unroll
        for (int h = 0; h < 2; ++h) {
            int row = r0 + h * 8;
            float bv = bias ? bias[row] : 0.f;
#pragma unroll
            for (int nb = 0; nb < 4; ++nb) {
                float v0 = C[mt][nb][2 * h] + bv, v1 = C[mt][nb][2 * h + 1] + bv;
                __nv_bfloat16 h0 = __float2bfloat16(v0), h1 = __float2bfloat16(v1);
                __nv_bfloat16 l0 = __float2bfloat16(v0 - __bfloat162float(h0));
                __nv_bfloat16 l1 = __float2bfloat16(v1 - __bfloat162float(h1));
                long e = (long)row * rstr + c0 + nb * 8;
                *(uint32_t*)(ph + e) = pkbf(h0, h1);
                *(uint32_t*)(pl + e) = pkbf(l0, l1);
            }
        }
    }
}
__device__ __forceinline__ void store_f32(float (&C)[2][4][4], float* __restrict__ out,
        long rstr, const float* __restrict__ bias, int lane, int wm, int wn) {
    const int c0 = wn * 32 + 2 * (lane & 3);
#pragma unroll
    for (int mt = 0; mt < 2; ++mt) {
        int r0 = wm * 32 + mt * 16 + (lane >> 2);
#pragma unroll
        for (int h = 0; h < 2; ++h) {
            int row = r0 + h * 8;
            float bv = bias ? bias[row] : 0.f;
#pragma unroll
            for (int nb = 0; nb < 4; ++nb)
                *(float2*)(out + (long)row * rstr + c0 + nb * 8) =
                    make_float2(C[mt][nb][2 * h] + bv, C[mt][nb][2 * h + 1] + bv);
        }
    }
}

// ---------------- K0: weight prep -------------------------------------------
__global__ void prep_w(const float* s0, const float* s1, const float* s2,
                       const float* s3, const float* s4, const float* s5,
                       const float* s6, const float* s7) {
    const float* srcs[8] = {s0, s1, s2, s3, s4, s5, s6, s7};
    const int offs[9] = {W_R, W_QW, W_KW, W_VW, W_QH, W_KH, W_VH, W_O, 163840};
    int m = blockIdx.y;
    const float* s = srcs[m];
    int base = offs[m], n = offs[m + 1] - offs[m];
    for (int i = blockIdx.x * blockDim.x + threadIdx.x; i < n;
         i += gridDim.x * blockDim.x) {
        float v = s[i];
        __nv_bfloat16 h = __float2bfloat16(v);
        g_wth[base + i] = h;
        g_wtl[base + i] = __float2bfloat16(v - __bfloat162float(h));
    }
}

// ---------------- K1: resize conv (K=256) ------------------------------------
// grid (128, 1, 8).  out planes resized[b][r][s], r-rows, s cols.
__global__ void __launch_bounds__(512, 1)
conv_resize(const float* __restrict__ x, const float* __restrict__ bias) {
    extern __shared__ char sm[];
    const int tid = threadIdx.x, lane = tid & 31, w = tid >> 5;
    const int wm = w >> 2, wn = w & 3;
    const uint32_t su = smem_u32(sm);
    const int n0 = blockIdx.x * 128, b = blockIdx.z;

    float C[2][4][4] = {};
    for (int kh = 0; kh < 2; ++kh) {
        cpa_tile(su, g_wth + W_R + kh * 128, g_wtl + W_R + kh * 128, 256, tid);
        cpa_commit();
        load_hilo_f32(sm, PLANE, x + (size_t)b * 256 * SL + (size_t)kh * 128 * SL + n0,
                      SL, tid);
        cpa_wait<0>();
        __syncthreads();
        wgemm<true>(su, su + PLANE, C, lane, wm, wn);
        __syncthreads();
    }
    long base = (size_t)b * 128 * SL + n0;
    store_planes(C, g_resh + base, g_resl + base, SL, bias, lane, wm, wn);
}

// ---------------- K2: per-(b,r) QKV ------------------------------------------
// grid 1024 = b*128+r.  bt=1: width branch (B=KxN, trans), bt=0: height (NxK).
__global__ void __launch_bounds__(512, 1)
qkv_mma(const __nv_bfloat16* __restrict__ xh, const __nv_bfloat16* __restrict__ xl,
        int w0, int w1, int w2,
        const float* __restrict__ bq, const float* __restrict__ bk,
        const float* __restrict__ bv, int bt) {
    extern __shared__ char sm[];
    const int tid = threadIdx.x, lane = tid & 31, w = tid >> 5;
    const int wm = w >> 2, wn = w & 3;
    const uint32_t su = smem_u32(sm);
    const int slice = blockIdx.x;
    const int b = slice >> 7, r = slice & 127;
    const uint32_t A0 = su, A1 = su + PLANE, Bs = su + 2 * PLANE;

    cpa_tile(Bs, xh + (size_t)slice * SL, xl + (size_t)slice * SL, 128, tid);
    cpa_tile(A0, g_wth + w0, g_wtl + w0, 128, tid);
    cpa_commit();                                        // g0: X + Wq
    cpa_tile(A1, g_wth + w1, g_wtl + w1, 128, tid);
    cpa_commit();                                        // g1: Wk
    cpa_wait<1>();
    __syncthreads();

    long obase = (size_t)b * 128 * SL + (size_t)r * 128;

    float C0[2][4][4] = {};
    if (bt) wgemm<true>(A0, Bs, C0, lane, wm, wn);
    else    wgemm<false>(A0, Bs, C0, lane, wm, wn);
    store_planes(C0, g_qh + obase, g_ql + obase, SL, bq, lane, wm, wn);
    __syncthreads();                                     // all done reading A0
    cpa_tile(A0, g_wth + w2, g_wtl + w2, 128, tid);
    cpa_commit();                                        // g2: Wv
    cpa_wait<1>();
    __syncthreads();

    float C1[2][4][4] = {};
    if (bt) wgemm<true>(A1, Bs, C1, lane, wm, wn);
    else    wgemm<false>(A1, Bs, C1, lane, wm, wn);
    store_planes(C1, g_kh + obase, g_kl + obase, SL, bk, lane, wm, wn);
    cpa_wait<0>();
    __syncthreads();

    float C2[2][4][4] = {};
    if (bt) wgemm<true>(A0, Bs, C2, lane, wm, wn);
    else    wgemm<false>(A0, Bs, C2, lane, wm, wn);
    store_planes(C2, g_vh + obase, g_vl + obase, SL, bv, lane, wm, wn);
}

// ---------------- K3: per-(b,o) attention ------------------------------------
// grid 1024 = b*128+o.  mode0 -> wattn planes [b][r][o][w]; mode1 -> att2 fp32.
#define T_RED  208896
__global__ void __launch_bounds__(512, 1)
attn_mma(int mode) {
    extern __shared__ char sm[];
    const int tid = threadIdx.x, lane = tid & 31, w = tid >> 5;
    const int wm = w >> 2, wn = w & 3;
    const uint32_t su = smem_u32(sm);
    const int slice = blockIdx.x;
    const int b = slice >> 7, o = slice & 127;
    const uint32_t As = su, Bs = su + PLANE, Vs = su + 2 * PLANE;
    float* red  = (float*)(sm + T_RED);
    float* red2 = (float*)(sm + T_RED + 2048);
    const size_t sb = (size_t)slice * SL;

    cpa_tile(As, g_qh + sb, g_ql + sb, 128, tid);
    cpa_tile(Bs, g_kh + sb, g_kl + sb, 128, tid);
    cpa_commit();                                        // g0: Q + K
    cpa_tile(Vs, g_vh + sb, g_vl + sb, 128, tid);
    cpa_commit();                                        // g1: V
    cpa_wait<1>();
    __syncthreads();

    float C[2][4][4] = {};
    wgemm<false>(As, Bs, C, lane, wm, wn);               // S = Q K^T

    // ---- softmax over rows (quad shuffle + cross-warp smem reduce) ----
    int rows_[2][2];
    float mx_[2][2], inv_[2][2];
#pragma unroll
    for (int mt = 0; mt < 2; ++mt)
#pragma unroll
        for (int h = 0; h < 2; ++h) {
            int row = wm * 32 + mt * 16 + (lane >> 2) + h * 8;
            rows_[mt][h] = row;
            float m = -3.4e38f;
#pragma unroll
            for (int nb = 0; nb < 4; ++nb)
                m = fmaxf(m, fmaxf(C[mt][nb][2 * h], C[mt][nb][2 * h + 1]));
            m = fmaxf(m, __shfl_xor_sync(0xffffffffu, m, 1));
            m = fmaxf(m, __shfl_xor_sync(0xffffffffu, m, 2));
            if ((lane & 3) == 0) red[wn * 128 + row] = m;
        }
    __syncthreads();
#pragma unroll
    for (int mt = 0; mt < 2; ++mt)
#pragma unroll
        for (int h = 0; h < 2; ++h) {
            int row = rows_[mt][h];
            float m = fmaxf(fmaxf(red[row], red[128 + row]),
                            fmaxf(red[256 + row], red[384 + row]));
            mx_[mt][h] = m;
            float s = 0.f;
#pragma unroll
            for (int nb = 0; nb < 4; ++nb) {
                float e0 = __expf(C[mt][nb][2 * h] - m);
                float e1 = __expf(C[mt][nb][2 * h + 1] - m);
                C[mt][nb][2 * h] = e0;
                C[mt][nb][2 * h + 1] = e1;
                s += e0 + e1;
            }
            s += __shfl_xor_sync(0xffffffffu, s, 1);
            s += __shfl_xor_sync(0xffffffffu, s, 2);
            if ((lane & 3) == 0) red2[wn * 128 + row] = s;
        }
    __syncthreads();
#pragma unroll
    for (int mt = 0; mt < 2; ++mt)
#pragma unroll
        for (int h = 0; h < 2; ++h) {
            int row = rows_[mt][h];
            float s = red2[row] + red2[128 + row] + red2[256 + row] + red2[384 + row];
            inv_[mt][h] = 1.f / s;
        }
    // write P hi/lo into A tiles
    const int c0 = wn * 32 + 2 * (lane & 3);
#pragma unroll
    for (int mt = 0; mt < 2; ++mt)
#pragma unroll
        for (int h = 0; h < 2; ++h) {
            int row = rows_[mt][h];
            float iv = inv_[mt][h];
#pragma unroll
            for (int nb = 0; nb < 4; ++nb) {
                float p0 = C[mt][nb][2 * h] * iv, p1 = C[mt][nb][2 * h + 1] * iv;
                __nv_bfloat16 h0 = __float2bfloat16(p0), h1 = __float2bfloat16(p1);
                __nv_bfloat16 l0 = __float2bfloat16(p0 - __bfloat162float(h0));
                __nv_bfloat16 l1 = __float2bfloat16(p1 - __bfloat162float(h1));
                char* pp = sm + row * TP + (c0 + nb * 8) * 2;
                *(uint32_t*)pp = pkbf(h0, h1);
                *(uint32_t*)(pp + TILE_B) = pkbf(l0, l1);
            }
        }
    cpa_wait<0>();                                       // V landed
    __syncthreads();                                     // P visible to all

    float O[2][4][4] = {};
    wgemm<true>(As, Vs, O, lane, wm, wn);                // O = P V

    if (mode == 0) {
        long base = (size_t)b * 128 * SL + (size_t)o * 128;   // [b][r][o][w]
        store_planes(O, g_wah + base, g_wal + base, SL, nullptr, lane, wm, wn);
    } else {
        store_f32(O, g_att2 + sb, 128, nullptr, lane, wm, wn);  // [b][o][r][h]
    }
}

// ---------------- K4: transpose att2 -> h_attn planes ------------------------
// in[b][o][r][h] fp32 -> planes [b][r][h*128+o]
__global__ void trans_k(const float* __restrict__ in) {
    __shared__ float t[32][33];
    const int slice = blockIdx.z;
    const int b = slice >> 7, r = slice & 127;
    const int o0 = blockIdx.x * 32, h0 = blockIdx.y * 32;
#pragma unroll
    for (int i = threadIdx.y; i < 32; i += 8)
        t[i][threadIdx.x] =
            in[(((size_t)b * 128 + o0 + i) * 128 + r) * 128 + h0 + threadIdx.x];
    __syncthreads();
#pragma unroll
    for (int i = threadIdx.y; i < 32; i += 8) {
        float v = t[threadIdx.x][i];
        size_t e = ((size_t)b * 128 + r) * SL + (h0 + i) * 128 + o0 + threadIdx.x;
        __nv_bfloat16 h = __float2bfloat16(v);
        g_hah[e] = h;
        g_hal[e] = __float2bfloat16(v - __bfloat162float(h));
    }
}

// ---------------- K5: restore conv (K=128, M=256) ----------------------------
// grid (128, 2, 8)
__global__ void __launch_bounds__(512, 1)
conv_restore(float* __restrict__ out, const float* __restrict__ bias) {
    extern __shared__ char sm[];
    const int tid = threadIdx.x, lane = tid & 31, w = tid >> 5;
    const int wm = w >> 2, wn = w & 3;
    const uint32_t su = smem_u32(sm);
    const int n0 = blockIdx.x * 128, m0 = blockIdx.y * 128, b = blockIdx.z;

    cpa_tile(su, g_wth + W_O + m0 * 128, g_wtl + W_O + m0 * 128, 128, tid);
    cpa_tile(su + PLANE, g_hah + (size_t)b * 128 * SL + n0,
             g_hal + (size_t)b * 128 * SL + n0, SL, tid);
    cpa_commit();
    cpa_wait<0>();
    __syncthreads();

    float C[2][4][4] = {};
    wgemm<true>(su, su + PLANE, C, lane, wm, wn);
    store_f32(C, out + (size_t)b * 256 * SL + (size_t)m0 * SL + n0, SL,
              bias + m0, lane, wm, wn);
}

// ---------------------------------------------------------------------------
extern "C" void kernel_launch(void* const* d_in, const int* in_sizes, int n_in,
                              void* d_out, int out_size) {
    const float* x   = (const float*)d_in[0];
    const float* Wr  = (const float*)d_in[1];
    const float* br  = (const float*)d_in[2];
    const float* Wqw = (const float*)d_in[3];
    const float* bqw = (const float*)d_in[4];
    const float* Wkw = (const float*)d_in[5];
    const float* bkw = (const float*)d_in[6];
    const float* Wvw = (const float*)d_in[7];
    const float* bvw = (const float*)d_in[8];
    const float* Wqh = (const float*)d_in[9];
    const float* bqh = (const float*)d_in[10];
    const float* Wkh = (const float*)d_in[11];
    const float* bkh = (const float*)d_in[12];
    const float* Wvh = (const float*)d_in[13];
    const float* bvh = (const float*)d_in[14];
    const float* Wo  = (const float*)d_in[15];
    const float* bo  = (const float*)d_in[16];
    float* out = (float*)d_out;

    void* p;
    cudaGetSymbolAddress(&p, g_att2);
    float* att2 = (float*)p;
    void* prh; cudaGetSymbolAddress(&prh, g_resh);
    void* prl; cudaGetSymbolAddress(&prl, g_resl);
    void* pwh; cudaGetSymbolAddress(&pwh, g_wah);
    void* pwl; cudaGetSymbolAddress(&pwl, g_wal);

    const int SM_CONV = 2 * PLANE;             // 139264
    const int SM_QKV  = 3 * PLANE;             // 208896
    const int SM_ATT  = 3 * PLANE + 4096;      // 212992
    cudaFuncSetAttribute((const void*)conv_resize,
                         cudaFuncAttributeMaxDynamicSharedMemorySize, SM_CONV);
    cudaFuncSetAttribute((const void*)qkv_mma,
                         cudaFuncAttributeMaxDynamicSharedMemorySize, SM_QKV);
    cudaFuncSetAttribute((const void*)attn_mma,
                         cudaFuncAttributeMaxDynamicSharedMemorySize, SM_ATT);
    cudaFuncSetAttribute((const void*)conv_restore,
                         cudaFuncAttributeMaxDynamicSharedMemorySize, SM_CONV);

    // 0) weight prep
    prep_w<<<dim3(64, 8), 256>>>(Wr, Wqw, Wkw, Wvw, Wqh, Wkh, Wvh, Wo);
    // 1) resize conv
    conv_resize<<<dim3(128, 1, 8), 512, SM_CONV>>>(x, br);
    // 2) width qkv (bt=1)
    qkv_mma<<<1024, 512, SM_QKV>>>((const __nv_bfloat16*)prh, (const __nv_bfloat16*)prl,
                                   W_QW, W_KW, W_VW, bqw, bkw, bvw, 1);
    // 3) width attention -> wattn planes
    attn_mma<<<1024, 512, SM_ATT>>>(0);
    // 4) height qkv (bt=0)
    qkv_mma<<<1024, 512, SM_QKV>>>((const __nv_bfloat16*)pwh, (const __nv_bfloat16*)pwl,
                                   W_QH, W_KH, W_VH, bqh, bkh, bvh, 0);
    // 5) height attention -> att2 fp32
    attn_mma<<<1024, 512, SM_ATT>>>(1);
    // 6) transpose + convert -> h_attn planes
    trans_k<<<dim3(4, 4, 1024), dim3(32, 8)>>>(att2);
    // 7) restore conv -> out
    conv_restore<<<dim3(128, 2, 8), 512, SM_CONV>>>(out, bo);
}